// round 8
// baseline (speedup 1.0000x reference)
#include <cuda_runtime.h>
#include <cstdint>

// x: (16, 512, 32, 32) f32 | p_mu, p_logvar: (16384, 512) f32 | out: scalar f32
#define DD      512
#define HWSZ    1024
#define NN      16384
#define TPB     32              // tokens per block
#define STEPS   8               // 4 tokens per step
#define NBLOCKS 512
#define SROW    516             // padded row stride (floats) for x tile [4][SROW]

__device__ double g_sx[DD];
__device__ double g_sx2[DD];
__device__ double g_siv[DD];
__device__ double g_smuiv[DD];
__device__ double g_P;
__device__ double g_R;
__device__ int    g_done;       // arrival counter; reset by finalizer

__global__ __launch_bounds__(512, 2)
void club_fused(const float* __restrict__ x,
                const float* __restrict__ mu,
                const float* __restrict__ lv,
                float* __restrict__ out)
{
    const int tid  = threadIdx.x;
    const int lane = tid & 31;
    const int warp = tid >> 5;          // 0..15
    const int ts   = tid >> 7;          // token row 0..3
    const int dg   = tid & 127;         // d-group: d = 4*dg..4*dg+3

    const int i0  = blockIdx.x * TPB;
    const int b   = i0 >> 10;
    const int hw0 = i0 & (HWSZ - 1);
    const float* xbp = x + (size_t)b * DD * HWSZ + hw0;

    __shared__ float  xs[2][4 * SROW];  // x tiles: [token row 0..3][d]
    __shared__ double sred[16];
    __shared__ int    s_last;

    // ---- x loader role: thread owns d-row tid; one float4 (4 hw) per step ----
    const float* xlp = xbp + (size_t)tid * HWSZ;
    float sxl = 0.f, sx2l = 0.f;        // per-d x stats, accumulated at commit

    // warmup: tile 0 -> buf0; tiles 1,2 in regs (depth-2 pipeline)
    float4 xt_a = __ldg((const float4*)xlp);
    {
        sxl  += xt_a.x + xt_a.y + xt_a.z + xt_a.w;
        sx2l += xt_a.x*xt_a.x + xt_a.y*xt_a.y + xt_a.z*xt_a.z + xt_a.w*xt_a.w;
        float* bse = &xs[0][0];
        bse[0*SROW + tid] = xt_a.x; bse[1*SROW + tid] = xt_a.y;
        bse[2*SROW + tid] = xt_a.z; bse[3*SROW + tid] = xt_a.w;
    }
    xt_a = __ldg((const float4*)(xlp + 4));   // tile 1
    float4 xt_b = __ldg((const float4*)(xlp + 8));   // tile 2

    // ---- mu/lv depth-2 register pipeline (512B/warp coalesced) ----
    const size_t mb = (size_t)(i0 + ts) * DD + 4 * dg;
    float4 pm[2], pl[2];
    pm[0] = __ldg((const float4*)(mu + mb));
    pl[0] = __ldg((const float4*)(lv + mb));
    pm[1] = __ldg((const float4*)(mu + mb + 4 * DD));
    pl[1] = __ldg((const float4*)(lv + mb + 4 * DD));

    float v0=0.f,v1=0.f,v2=0.f,v3=0.f;   // iv sums per owned d
    float w0=0.f,w1=0.f,w2=0.f,w3=0.f;   // mu*iv sums per owned d
    float accP = 0.f, accR = 0.f;

#pragma unroll
    for (int s = 0; s < STEPS; s++) {
        __syncthreads();                 // tile s ready; buf[(s+1)&1] free

        // commit tile s+1 (from xt_a, loaded 2 steps ago), rotate pipeline
        if (s < STEPS - 1) {
            sxl  += xt_a.x + xt_a.y + xt_a.z + xt_a.w;
            sx2l += xt_a.x*xt_a.x + xt_a.y*xt_a.y + xt_a.z*xt_a.z + xt_a.w*xt_a.w;
            float* bse = &xs[(s + 1) & 1][0];
            bse[0*SROW + tid] = xt_a.x; bse[1*SROW + tid] = xt_a.y;
            bse[2*SROW + tid] = xt_a.z; bse[3*SROW + tid] = xt_a.w;
            xt_a = xt_b;
            if (s < STEPS - 3) xt_b = __ldg((const float4*)(xlp + 4 * (s + 3)));
        }

        const float4 cm = pm[s & 1];
        const float4 cl = pl[s & 1];
        if (s < STEPS - 2) {
            pm[s & 1] = __ldg((const float4*)(mu + mb + (size_t)(s + 2) * 4 * DD));
            pl[s & 1] = __ldg((const float4*)(lv + mb + (size_t)(s + 2) * 4 * DD));
        }

        // x for (token ts, d = 4dg..4dg+3): conflict-free LDS.128
        const float4 xv = *(const float4*)&xs[s & 1][ts * SROW + 4 * dg];

        const float i0v = __expf(-cl.x), i1v = __expf(-cl.y);
        const float i2v = __expf(-cl.z), i3v = __expf(-cl.w);

        float dx;
        dx = xv.x - cm.x; accP += dx*dx*i0v; accR += cm.x*cm.x*i0v; v0 += i0v; w0 += cm.x*i0v;
        dx = xv.y - cm.y; accP += dx*dx*i1v; accR += cm.y*cm.y*i1v; v1 += i1v; w1 += cm.y*i1v;
        dx = xv.z - cm.z; accP += dx*dx*i2v; accR += cm.z*cm.z*i2v; v2 += i2v; w2 += cm.z*i2v;
        dx = xv.w - cm.w; accP += dx*dx*i3v; accR += cm.w*cm.w*i3v; v3 += i3v; w3 += cm.w*i3v;
    }

    // ---- block-reduce P / R (fp64), one atomic each ----
    double dP = (double)accP, dR = (double)accR;
#pragma unroll
    for (int o = 16; o > 0; o >>= 1) {
        dP += __shfl_down_sync(0xffffffffu, dP, o);
        dR += __shfl_down_sync(0xffffffffu, dR, o);
    }
    if (lane == 0) sred[warp] = dP;
    __syncthreads();
    if (warp == 0) {
        double t = (lane < 16) ? sred[lane] : 0.0;
#pragma unroll
        for (int o = 8; o > 0; o >>= 1) t += __shfl_down_sync(0xffffffffu, t, o);
        if (lane == 0) atomicAdd(&g_P, t);
    }
    __syncthreads();
    if (lane == 0) sred[warp] = dR;
    __syncthreads();
    if (warp == 0) {
        double t = (lane < 16) ? sred[lane] : 0.0;
#pragma unroll
        for (int o = 8; o > 0; o >>= 1) t += __shfl_down_sync(0xffffffffu, t, o);
        if (lane == 0) atomicAdd(&g_R, t);
    }

    // ---- x stats: loader thread owns d = tid completely ----
    atomicAdd(&g_sx[tid],  (double)sxl);
    atomicAdd(&g_sx2[tid], (double)sx2l);

    // ---- iv / mu*iv: one SMEM round (4 rows), then fp64 atomics ----
    __syncthreads();                 // P/R phase syncs already passed; safe to reuse xs
    *(float4*)&xs[0][ts * SROW + 4 * dg] = make_float4(v0, v1, v2, v3);
    *(float4*)&xs[1][ts * SROW + 4 * dg] = make_float4(w0, w1, w2, w3);
    __syncthreads();
    {
        float s1 = 0.f, s2 = 0.f;
#pragma unroll
        for (int t = 0; t < 4; t++) { s1 += xs[0][t * SROW + tid]; s2 += xs[1][t * SROW + tid]; }
        atomicAdd(&g_siv[tid],   (double)s1);
        atomicAdd(&g_smuiv[tid], (double)s2);
    }

    // ---- fused finalize: last-arriving block combines & resets ----
    __threadfence();
    if (tid == 0) s_last = (atomicAdd(&g_done, 1) == NBLOCKS - 1) ? 1 : 0;
    __syncthreads();
    if (s_last) {
        __threadfence();
        const double invN = 1.0 / (double)NN;
        double q = (g_sx2[tid] * invN) * g_siv[tid]
                 - 2.0 * (g_sx[tid] * invN) * g_smuiv[tid];
        g_sx[tid] = 0.0; g_sx2[tid] = 0.0; g_siv[tid] = 0.0; g_smuiv[tid] = 0.0;
#pragma unroll
        for (int o = 16; o > 0; o >>= 1) q += __shfl_down_sync(0xffffffffu, q, o);
        if (lane == 0) sred[warp] = q;
        __syncthreads();
        if (warp == 0) {
            double t = (lane < 16) ? sred[lane] : 0.0;
#pragma unroll
            for (int o = 8; o > 0; o >>= 1) t += __shfl_down_sync(0xffffffffu, t, o);
            if (lane == 0) {
                const double Q = t + g_R;
                out[0] = (float)(-0.5 * invN * (g_P - Q));
                g_P = 0.0; g_R = 0.0; g_done = 0;
            }
        }
    }
}

extern "C" void kernel_launch(void* const* d_in, const int* in_sizes, int n_in,
                              void* d_out, int out_size)
{
    const float* x  = (const float*)d_in[0];
    const float* mu = (const float*)d_in[1];
    const float* lv = (const float*)d_in[2];
    float* out = (float*)d_out;

    club_fused<<<NBLOCKS, 512>>>(x, mu, lv, out);
}